// round 1
// baseline (speedup 1.0000x reference)
#include <cuda_runtime.h>
#include <cuda_bf16.h>
#include <math.h>

#define N_NODES 100000
#define N_EDGES 400000
#define N_GRAPHS 2500
#define DIM 128
#define F_IN 78
#define BN_EPS 1e-5f

// ---------------- scratch (device globals; no allocation) ----------------
__device__ float g_t0[N_NODES * DIM];
__device__ float g_t1[N_NODES * DIM];
__device__ float g_g1[N_NODES * DIM];
__device__ float g_g2[N_NODES * DIM];
__device__ float g_h1[N_NODES * DIM];
__device__ float g_h2[N_NODES * DIM];
__device__ float g_h3[N_NODES * DIM];

__device__ int   g_cnt[N_NODES];       // in-degree (edges only)
__device__ float g_dis[N_NODES];       // rsqrt(in-degree + 1)
__device__ int   g_rowptr[N_NODES + 1];
__device__ int   g_cursor[N_NODES];    // scan temp, then scatter cursor
__device__ int   g_csrc[N_EDGES];      // CSR: src sorted by dst
__device__ int   g_blksums[256];
__device__ float g_sum[DIM], g_sumsq[DIM];
__device__ float g_mu[DIM], g_istd[DIM];
__device__ int   g_gstart[N_GRAPHS + 1];

// ---------------- degree / CSR build ----------------
__global__ void k_zero_cnt() {
    int i = blockIdx.x * blockDim.x + threadIdx.x;
    if (i < N_NODES) g_cnt[i] = 0;
}

__global__ void k_hist(const int* __restrict__ dst) {
    int e = blockIdx.x * blockDim.x + threadIdx.x;
    if (e < N_EDGES) atomicAdd(&g_cnt[dst[e]], 1);
}

__global__ void k_dis() {
    int i = blockIdx.x * blockDim.x + threadIdx.x;
    if (i < N_NODES) g_dis[i] = rsqrtf((float)(g_cnt[i] + 1));
}

// per-chunk inclusive scan of g_cnt -> g_cursor, block sums -> g_blksums
__global__ void k_scan1() {
    __shared__ int s[1024];
    int tid = threadIdx.x;
    int i = blockIdx.x * 1024 + tid;
    int v = (i < N_NODES) ? g_cnt[i] : 0;
    s[tid] = v;
    __syncthreads();
    for (int off = 1; off < 1024; off <<= 1) {
        int t = (tid >= off) ? s[tid - off] : 0;
        __syncthreads();
        s[tid] += t;
        __syncthreads();
    }
    if (i < N_NODES) g_cursor[i] = s[tid];
    if (tid == 1023) g_blksums[blockIdx.x] = s[1023];
}

__global__ void k_scan2(int nblocks) {
    if (threadIdx.x == 0 && blockIdx.x == 0) {
        int run = 0;
        for (int b = 0; b < nblocks; b++) {
            int t = g_blksums[b];
            g_blksums[b] = run;
            run += t;
        }
    }
}

__global__ void k_scan3() {
    int i = blockIdx.x * blockDim.x + threadIdx.x;
    if (i < N_NODES) {
        int val = g_cursor[i] + g_blksums[i >> 10];  // inclusive scan
        g_rowptr[i + 1] = val;
        g_cursor[i] = val - g_cnt[i];                // exclusive = row start
        if (i == 0) g_rowptr[0] = 0;
    }
}

__global__ void k_scatter(const int* __restrict__ src, const int* __restrict__ dst) {
    int e = blockIdx.x * blockDim.x + threadIdx.x;
    if (e < N_EDGES) {
        int d = dst[e];
        int pos = atomicAdd(&g_cursor[d], 1);
        g_csrc[pos] = src[e];
    }
}

// graph start offsets via binary search over sorted batch
__global__ void k_gstart(const int* __restrict__ batch) {
    int g = blockIdx.x * blockDim.x + threadIdx.x;
    if (g <= N_GRAPHS) {
        int lo = 0, hi = N_NODES;
        while (lo < hi) {
            int mid = (lo + hi) >> 1;
            if (batch[mid] < g) lo = mid + 1; else hi = mid;
        }
        g_gstart[g] = lo;
    }
}

// ---------------- GEMM: C[N_NODES x 128] = A[N_NODES x K] @ W[K x 128] ----------------
#define TILE_M 64
#define KC 32

template <int K, bool BIAS, bool RELU>
__global__ void __launch_bounds__(256) k_gemm(const float* __restrict__ A,
                                              const float* __restrict__ W,
                                              const float* __restrict__ bias,
                                              float* __restrict__ C) {
    __shared__ float Bs[KC * DIM];            // 16 KB
    __shared__ float As[TILE_M * (KC + 1)];   // 8.25 KB
    const int tid = threadIdx.x;
    const int tx = tid & 15;   // col group: cols 8*tx .. 8*tx+7
    const int ty = tid >> 4;   // row group: rows 4*ty .. 4*ty+3
    const int row0 = blockIdx.x * TILE_M;

    float acc[4][8];
#pragma unroll
    for (int i = 0; i < 4; i++)
#pragma unroll
        for (int j = 0; j < 8; j++) acc[i][j] = 0.f;

    for (int kk = 0; kk < K; kk += KC) {
        // load A tile (64 x 32), zero-padded
#pragma unroll
        for (int t = 0; t < (TILE_M * KC) / 256; t++) {
            int idx = tid + t * 256;
            int r = idx >> 5, c = idx & 31;
            int grow = row0 + r, gcol = kk + c;
            float v = 0.f;
            if (grow < N_NODES && gcol < K) v = A[grow * K + gcol];
            As[r * (KC + 1) + c] = v;
        }
        // load W tile (32 x 128), zero-padded
#pragma unroll
        for (int t = 0; t < (KC * DIM) / 256; t++) {
            int idx = tid + t * 256;
            int k = idx >> 7, c = idx & 127;
            int gk = kk + k;
            Bs[k * DIM + c] = (gk < K) ? W[gk * DIM + c] : 0.f;
        }
        __syncthreads();
#pragma unroll 8
        for (int k = 0; k < KC; k++) {
            float4 b0 = *(const float4*)&Bs[k * DIM + tx * 8];
            float4 b1 = *(const float4*)&Bs[k * DIM + tx * 8 + 4];
#pragma unroll
            for (int i = 0; i < 4; i++) {
                float a = As[(ty * 4 + i) * (KC + 1) + k];
                acc[i][0] += a * b0.x; acc[i][1] += a * b0.y;
                acc[i][2] += a * b0.z; acc[i][3] += a * b0.w;
                acc[i][4] += a * b1.x; acc[i][5] += a * b1.y;
                acc[i][6] += a * b1.z; acc[i][7] += a * b1.w;
            }
        }
        __syncthreads();
    }

    float bv[8];
#pragma unroll
    for (int j = 0; j < 8; j++) bv[j] = BIAS ? bias[tx * 8 + j] : 0.f;

#pragma unroll
    for (int i = 0; i < 4; i++) {
        int row = row0 + ty * 4 + i;
        if (row < N_NODES) {
            float4 o0, o1;
            o0.x = acc[i][0] + bv[0]; o0.y = acc[i][1] + bv[1];
            o0.z = acc[i][2] + bv[2]; o0.w = acc[i][3] + bv[3];
            o1.x = acc[i][4] + bv[4]; o1.y = acc[i][5] + bv[5];
            o1.z = acc[i][6] + bv[6]; o1.w = acc[i][7] + bv[7];
            if (RELU) {
                o0.x = fmaxf(o0.x, 0.f); o0.y = fmaxf(o0.y, 0.f);
                o0.z = fmaxf(o0.z, 0.f); o0.w = fmaxf(o0.w, 0.f);
                o1.x = fmaxf(o1.x, 0.f); o1.y = fmaxf(o1.y, 0.f);
                o1.z = fmaxf(o1.z, 0.f); o1.w = fmaxf(o1.w, 0.f);
            }
            *(float4*)&C[row * DIM + tx * 8] = o0;
            *(float4*)&C[row * DIM + tx * 8 + 4] = o1;
        }
    }
}

// ---------------- GCN aggregation: out = relu(dis_i*(h_i*dis_i + sum h_s*dis_s) + b) ----------------
__global__ void k_gcn_agg(const float* __restrict__ h, const float* __restrict__ bias,
                          float* __restrict__ out) {
    int gt = blockIdx.x * blockDim.x + threadIdx.x;
    int node = gt >> 5;
    int lane = gt & 31;
    if (node >= N_NODES) return;
    float dn = g_dis[node];
    float4 acc = *(const float4*)&h[node * DIM + lane * 4];
    acc.x *= dn; acc.y *= dn; acc.z *= dn; acc.w *= dn;
    int e0 = g_rowptr[node], e1 = g_rowptr[node + 1];
    for (int e = e0; e < e1; e++) {
        int s = g_csrc[e];
        float ds = g_dis[s];
        float4 v = *(const float4*)&h[s * DIM + lane * 4];
        acc.x += v.x * ds; acc.y += v.y * ds;
        acc.z += v.z * ds; acc.w += v.w * ds;
    }
    float4 b = *(const float4*)&bias[lane * 4];
    float4 r;
    r.x = fmaxf(acc.x * dn + b.x, 0.f);
    r.y = fmaxf(acc.y * dn + b.y, 0.f);
    r.z = fmaxf(acc.z * dn + b.z, 0.f);
    r.w = fmaxf(acc.w * dn + b.w, 0.f);
    *(float4*)&out[node * DIM + lane * 4] = r;
}

// ---------------- GIN aggregation (DIM=128): u = h + sum_{in} h[src] ----------------
__global__ void k_gin_agg128(const float* __restrict__ h, float* __restrict__ out) {
    int gt = blockIdx.x * blockDim.x + threadIdx.x;
    int node = gt >> 5;
    int lane = gt & 31;
    if (node >= N_NODES) return;
    float4 acc = *(const float4*)&h[node * DIM + lane * 4];
    int e0 = g_rowptr[node], e1 = g_rowptr[node + 1];
    for (int e = e0; e < e1; e++) {
        int s = g_csrc[e];
        float4 v = *(const float4*)&h[s * DIM + lane * 4];
        acc.x += v.x; acc.y += v.y; acc.z += v.z; acc.w += v.w;
    }
    *(float4*)&out[node * DIM + lane * 4] = acc;
}

// ---------------- GIN aggregation (F_IN=78, scalar lanes) ----------------
__global__ void k_gin_agg78(const float* __restrict__ x, float* __restrict__ out) {
    int gt = blockIdx.x * blockDim.x + threadIdx.x;
    int node = gt >> 5;
    int lane = gt & 31;
    if (node >= N_NODES) return;
    bool has2 = (lane + 64) < F_IN;
    float a0 = x[node * F_IN + lane];
    float a1 = x[node * F_IN + lane + 32];
    float a2 = has2 ? x[node * F_IN + lane + 64] : 0.f;
    int e0 = g_rowptr[node], e1 = g_rowptr[node + 1];
    for (int e = e0; e < e1; e++) {
        int s = g_csrc[e];
        a0 += x[s * F_IN + lane];
        a1 += x[s * F_IN + lane + 32];
        if (has2) a2 += x[s * F_IN + lane + 64];
    }
    out[node * F_IN + lane] = a0;
    out[node * F_IN + lane + 32] = a1;
    if (has2) out[node * F_IN + lane + 64] = a2;
}

// ---------------- batchnorm ----------------
__global__ void k_bn_zero() {
    int c = threadIdx.x;
    if (c < DIM) { g_sum[c] = 0.f; g_sumsq[c] = 0.f; }
}

#define BN_ROWS_PER 250
__global__ void k_bn_stats(const float* __restrict__ h) {
    int c = threadIdx.x;  // 128
    int r0 = blockIdx.x * BN_ROWS_PER;
    int r1 = r0 + BN_ROWS_PER;
    if (r1 > N_NODES) r1 = N_NODES;
    float s = 0.f, s2 = 0.f;
    for (int r = r0; r < r1; r++) {
        float v = h[r * DIM + c];
        s += v; s2 += v * v;
    }
    atomicAdd(&g_sum[c], s);
    atomicAdd(&g_sumsq[c], s2);
}

__global__ void k_bn_final() {
    int c = threadIdx.x;
    if (c < DIM) {
        float mu = g_sum[c] * (1.f / N_NODES);
        float var = g_sumsq[c] * (1.f / N_NODES) - mu * mu;
        g_mu[c] = mu;
        g_istd[c] = rsqrtf(var + BN_EPS);
    }
}

__global__ void k_bn_apply(const float* __restrict__ h, const float* __restrict__ gamma,
                           const float* __restrict__ beta, float* __restrict__ out) {
    int tid = threadIdx.x;            // 256
    int c = tid & 127;
    int r = blockIdx.x * 2 + (tid >> 7);
    if (r < N_NODES) {
        float v = h[r * DIM + c];
        out[r * DIM + c] = (v - g_mu[c]) * g_istd[c] * gamma[c] + beta[c];
    }
}

// ---------------- readout: segment_max over 9*128-wide rep ----------------
__global__ void k_readout(float* __restrict__ out) {
    int g = blockIdx.x;
    int c = threadIdx.x;  // 128
    int r0 = g_gstart[g], r1 = g_gstart[g + 1];
    float m1 = -INFINITY, m2 = -INFINITY, m3 = -INFINITY;
    float m4 = -INFINITY, m5 = -INFINITY, m6 = -INFINITY;
    float m7 = -INFINITY, m8 = -INFINITY, m9 = -INFINITY;
    for (int r = r0; r < r1; r++) {
        float a = g_h1[r * DIM + c];
        float b = g_h2[r * DIM + c];
        float d = g_h3[r * DIM + c];
        float e1 = g_g1[r * DIM + c];
        float e2 = g_g2[r * DIM + c];
        m1 = fmaxf(m1, a); m2 = fmaxf(m2, b); m3 = fmaxf(m3, d);
        m4 = fmaxf(m4, a * b * d);
        m5 = fmaxf(m5, a + b + d);
        m6 = fmaxf(m6, e1); m7 = fmaxf(m7, e2);
        m8 = fmaxf(m8, e2 + e1); m9 = fmaxf(m9, e2 * e1);
    }
    float* o = out + (size_t)g * (9 * DIM);
    o[0 * DIM + c] = m1; o[1 * DIM + c] = m2; o[2 * DIM + c] = m3;
    o[3 * DIM + c] = m4; o[4 * DIM + c] = m5; o[5 * DIM + c] = m6;
    o[6 * DIM + c] = m7; o[7 * DIM + c] = m8; o[8 * DIM + c] = m9;
}

// ---------------- launch ----------------
extern "C" void kernel_launch(void* const* d_in, const int* in_sizes, int n_in,
                              void* d_out, int out_size) {
    const float* x = (const float*)d_in[0];
    const int* ei = (const int*)d_in[1];
    const int* src = ei;
    const int* dst = ei + N_EDGES;
    const int* batch = (const int*)d_in[2];
    int base = (n_in >= 18) ? 4 : 3;  // num_graphs may occupy a slot
    const float* gcn1_W = (const float*)d_in[base + 0];
    const float* gcn1_b = (const float*)d_in[base + 1];
    const float* gcn2_W = (const float*)d_in[base + 2];
    const float* gcn2_b = (const float*)d_in[base + 3];
    const float* gin0_w1 = (const float*)d_in[base + 4];
    const float* gin0_b1 = (const float*)d_in[base + 5];
    const float* gin0_w2 = (const float*)d_in[base + 6];
    const float* gin0_b2 = (const float*)d_in[base + 7];
    const float* gin_w1 = (const float*)d_in[base + 8];   // [2,128,128]
    const float* gin_b1 = (const float*)d_in[base + 9];   // [2,128]
    const float* gin_w2 = (const float*)d_in[base + 10];
    const float* gin_b2 = (const float*)d_in[base + 11];
    const float* bn_gamma = (const float*)d_in[base + 12]; // [3,128]
    const float* bn_beta = (const float*)d_in[base + 13];
    float* out = (float*)d_out;

    float* t0 = nullptr; float* t1 = nullptr;
    float* g1 = nullptr; float* g2 = nullptr;
    float* h1 = nullptr; float* h2 = nullptr; float* h3 = nullptr;
    cudaGetSymbolAddress((void**)&t0, g_t0);
    cudaGetSymbolAddress((void**)&t1, g_t1);
    cudaGetSymbolAddress((void**)&g1, g_g1);
    cudaGetSymbolAddress((void**)&g2, g_g2);
    cudaGetSymbolAddress((void**)&h1, g_h1);
    cudaGetSymbolAddress((void**)&h2, g_h2);
    cudaGetSymbolAddress((void**)&h3, g_h3);

    const int NB_N = (N_NODES + 255) / 256;
    const int NB_E = (N_EDGES + 255) / 256;
    const int NB_GEMM = (N_NODES + TILE_M - 1) / TILE_M;
    const int NB_AGG = (N_NODES * 32 + 255) / 256;
    const int SCAN_BLOCKS = (N_NODES + 1023) / 1024;

    // --- CSR build + degrees ---
    k_zero_cnt<<<NB_N, 256>>>();
    k_hist<<<NB_E, 256>>>(dst);
    k_dis<<<NB_N, 256>>>();
    k_scan1<<<SCAN_BLOCKS, 1024>>>();
    k_scan2<<<1, 1>>>(SCAN_BLOCKS);
    k_scan3<<<NB_N, 256>>>();
    k_scatter<<<NB_E, 256>>>(src, dst);
    k_gstart<<<(N_GRAPHS + 1 + 255) / 256, 256>>>(batch);

    // --- GCN1: g1 = relu(agg(x@W1) + b1) ---
    k_gemm<F_IN, false, false><<<NB_GEMM, 256>>>(x, gcn1_W, nullptr, t0);
    k_gcn_agg<<<NB_AGG, 256>>>(t0, gcn1_b, g1);
    // --- GCN2: g2 = relu(agg(g1@W2) + b2) ---
    k_gemm<DIM, false, false><<<NB_GEMM, 256>>>(g1, gcn2_W, nullptr, t0);
    k_gcn_agg<<<NB_AGG, 256>>>(t0, gcn2_b, g2);

    // --- GIN layer 0 (input x, 78-dim) ---
    k_gin_agg78<<<NB_AGG, 256>>>(x, t1);                                   // u = x + agg (stride 78)
    k_gemm<F_IN, true, true><<<NB_GEMM, 256>>>(t1, gin0_w1, gin0_b1, t0);  // z = relu(u@w1+b1)
    k_gemm<DIM, true, true><<<NB_GEMM, 256>>>(t0, gin0_w2, gin0_b2, t1);   // r = relu(z@w2+b2)
    k_bn_zero<<<1, 128>>>();
    k_bn_stats<<<(N_NODES + BN_ROWS_PER - 1) / BN_ROWS_PER, 128>>>(t1);
    k_bn_final<<<1, 128>>>();
    k_bn_apply<<<(N_NODES + 1) / 2, 256>>>(t1, bn_gamma + 0 * DIM, bn_beta + 0 * DIM, h1);

    // --- GIN layer 1 ---
    k_gin_agg128<<<NB_AGG, 256>>>(h1, t0);
    k_gemm<DIM, true, true><<<NB_GEMM, 256>>>(t0, gin_w1 + 0 * DIM * DIM, gin_b1 + 0 * DIM, t1);
    k_gemm<DIM, true, true><<<NB_GEMM, 256>>>(t1, gin_w2 + 0 * DIM * DIM, gin_b2 + 0 * DIM, t0);
    k_bn_zero<<<1, 128>>>();
    k_bn_stats<<<(N_NODES + BN_ROWS_PER - 1) / BN_ROWS_PER, 128>>>(t0);
    k_bn_final<<<1, 128>>>();
    k_bn_apply<<<(N_NODES + 1) / 2, 256>>>(t0, bn_gamma + 1 * DIM, bn_beta + 1 * DIM, h2);

    // --- GIN layer 2 ---
    k_gin_agg128<<<NB_AGG, 256>>>(h2, t1);
    k_gemm<DIM, true, true><<<NB_GEMM, 256>>>(t1, gin_w1 + 1 * DIM * DIM, gin_b1 + 1 * DIM, t0);
    k_gemm<DIM, true, true><<<NB_GEMM, 256>>>(t0, gin_w2 + 1 * DIM * DIM, gin_b2 + 1 * DIM, t1);
    k_bn_zero<<<1, 128>>>();
    k_bn_stats<<<(N_NODES + BN_ROWS_PER - 1) / BN_ROWS_PER, 128>>>(t1);
    k_bn_final<<<1, 128>>>();
    k_bn_apply<<<(N_NODES + 1) / 2, 256>>>(t1, bn_gamma + 2 * DIM, bn_beta + 2 * DIM, h3);

    // --- readout ---
    k_readout<<<N_GRAPHS, 128>>>(out);
}

// round 3
// speedup vs baseline: 1.4417x; 1.4417x over previous
#include <cuda_runtime.h>
#include <cuda_bf16.h>
#include <math.h>

#define N_NODES 100000
#define N_EDGES 400000
#define N_GRAPHS 2500
#define DIM 128
#define F_IN 78
#define BN_EPS 1e-5f

// ---------------- scratch (device globals; no allocation) ----------------
__device__ float g_t0[N_NODES * DIM];
__device__ float g_t1[N_NODES * DIM];
__device__ float g_g1[N_NODES * DIM];
__device__ float g_g2[N_NODES * DIM];
__device__ float g_z1[N_NODES * DIM];   // raw relu(gin) outputs, pre-BN-affine
__device__ float g_z2[N_NODES * DIM];
__device__ float g_z3[N_NODES * DIM];

__device__ int   g_cnt[N_NODES];
__device__ float g_dis[N_NODES];
__device__ int   g_rowptr[N_NODES + 1];
__device__ int   g_cursor[N_NODES];
__device__ int   g_csrc[N_EDGES];
__device__ int   g_blksums[256];
__device__ float g_sum[3 * DIM], g_sumsq[3 * DIM];
__device__ float g_a[3 * DIM], g_b[3 * DIM];   // folded BN affine: h = a*z + b
__device__ int   g_gstart[N_GRAPHS + 1];

// ---------------- f32x2 packed helpers ----------------
__device__ __forceinline__ unsigned long long pack2(float lo, float hi) {
    unsigned long long r;
    asm("mov.b64 %0, {%1, %2};" : "=l"(r) : "f"(lo), "f"(hi));
    return r;
}
__device__ __forceinline__ void unpack2(unsigned long long v, float& lo, float& hi) {
    asm("mov.b64 {%0, %1}, %2;" : "=f"(lo), "=f"(hi) : "l"(v));
}
__device__ __forceinline__ unsigned long long fma2(unsigned long long a,
                                                   unsigned long long b,
                                                   unsigned long long c) {
    unsigned long long d;
    asm("fma.rn.f32x2 %0, %1, %2, %3;" : "=l"(d) : "l"(a), "l"(b), "l"(c));
    return d;
}

// ---------------- init: zero degree counters + BN stats ----------------
__global__ void k_init() {
    int i = blockIdx.x * blockDim.x + threadIdx.x;
    if (i < N_NODES) g_cnt[i] = 0;
    if (i < 3 * DIM) { g_sum[i] = 0.f; g_sumsq[i] = 0.f; }
}

__global__ void k_hist(const int* __restrict__ dst) {
    int e = blockIdx.x * blockDim.x + threadIdx.x;
    if (e < N_EDGES) atomicAdd(&g_cnt[dst[e]], 1);
}

__global__ void k_dis() {
    int i = blockIdx.x * blockDim.x + threadIdx.x;
    if (i < N_NODES) g_dis[i] = rsqrtf((float)(g_cnt[i] + 1));
}

__global__ void k_scan1() {
    __shared__ int s[1024];
    int tid = threadIdx.x;
    int i = blockIdx.x * 1024 + tid;
    int v = (i < N_NODES) ? g_cnt[i] : 0;
    s[tid] = v;
    __syncthreads();
    for (int off = 1; off < 1024; off <<= 1) {
        int t = (tid >= off) ? s[tid - off] : 0;
        __syncthreads();
        s[tid] += t;
        __syncthreads();
    }
    if (i < N_NODES) g_cursor[i] = s[tid];
    if (tid == 1023) g_blksums[blockIdx.x] = s[1023];
}

__global__ void k_scan2(int nblocks) {
    if (threadIdx.x == 0 && blockIdx.x == 0) {
        int run = 0;
        for (int b = 0; b < nblocks; b++) {
            int t = g_blksums[b];
            g_blksums[b] = run;
            run += t;
        }
    }
}

__global__ void k_scan3() {
    int i = blockIdx.x * blockDim.x + threadIdx.x;
    if (i < N_NODES) {
        int val = g_cursor[i] + g_blksums[i >> 10];
        g_rowptr[i + 1] = val;
        g_cursor[i] = val - g_cnt[i];
        if (i == 0) g_rowptr[0] = 0;
    }
}

__global__ void k_scatter(const int* __restrict__ src, const int* __restrict__ dst) {
    int e = blockIdx.x * blockDim.x + threadIdx.x;
    if (e < N_EDGES) {
        int d = dst[e];
        int pos = atomicAdd(&g_cursor[d], 1);
        g_csrc[pos] = src[e];
    }
}

__global__ void k_gstart(const int* __restrict__ batch) {
    int g = blockIdx.x * blockDim.x + threadIdx.x;
    if (g <= N_GRAPHS) {
        int lo = 0, hi = N_NODES;
        while (lo < hi) {
            int mid = (lo + hi) >> 1;
            if (batch[mid] < g) lo = mid + 1; else hi = mid;
        }
        g_gstart[g] = lo;
    }
}

// ---------------- GEMM: C[100000 x 128] = A[. x K] @ W[K x 128] ----------------
// 128x128 tile, 256 threads, 8x8 per thread via packed f32x2 FMA.
#define TM 128
#define KC 32

template <int K, bool BIAS, bool RELU, int STATS>
__global__ void __launch_bounds__(256) k_gemm(const float* __restrict__ A,
                                              const float* __restrict__ W,
                                              const float* __restrict__ bias,
                                              float* __restrict__ C) {
    __shared__ float As[KC][TM + 4];       // row stride 132 floats (16B aligned)
    __shared__ float Bs[KC][DIM];
    __shared__ float Sred[(STATS >= 0) ? 16 : 1][DIM];

    const int tid = threadIdx.x;
    const int tx = tid & 15;   // 8 cols: tx*8 .. tx*8+7
    const int ty = tid >> 4;   // 8 rows: ty*4..+3 and 64+ty*4..+3
    const int row0 = blockIdx.x * TM;

    unsigned long long acc[8][4];
#pragma unroll
    for (int i = 0; i < 8; i++)
#pragma unroll
        for (int j = 0; j < 4; j++) acc[i][j] = 0ull;

    constexpr int KSTEPS = (K + KC - 1) / KC;
    for (int s = 0; s < KSTEPS; s++) {
        const int kk = s * KC;
        // --- load A tile (TM x KC), transposed into As[k][m] ---
        if constexpr (K % KC == 0) {
            // vectorized path (K multiple of 32 -> rows 16B aligned)
#pragma unroll
            for (int t = 0; t < 4; t++) {
                int idx = tid + t * 256;       // 1024 float4
                int r = idx >> 3, c4 = idx & 7;
                float4 v = make_float4(0.f, 0.f, 0.f, 0.f);
                int grow = row0 + r;
                if (grow < N_NODES) v = *(const float4*)&A[grow * K + kk + c4 * 4];
                As[c4 * 4 + 0][r] = v.x;
                As[c4 * 4 + 1][r] = v.y;
                As[c4 * 4 + 2][r] = v.z;
                As[c4 * 4 + 3][r] = v.w;
            }
        } else {
#pragma unroll
            for (int t = 0; t < 16; t++) {
                int idx = tid + t * 256;       // 4096 scalars
                int r = idx >> 5, c = idx & 31;
                int grow = row0 + r, gcol = kk + c;
                float v = 0.f;
                if (grow < N_NODES && gcol < K) v = A[grow * K + gcol];
                As[c][r] = v;
            }
        }
        // --- load B tile (KC x 128) ---
#pragma unroll
        for (int t = 0; t < 4; t++) {
            int idx = tid + t * 256;           // 1024 float4
            int k = idx >> 5, c4 = idx & 31;
            int gk = kk + k;
            float4 v = make_float4(0.f, 0.f, 0.f, 0.f);
            if (gk < K) v = *(const float4*)&W[gk * DIM + c4 * 4];
            *(float4*)&Bs[k][c4 * 4] = v;
        }
        __syncthreads();

#pragma unroll 8
        for (int k = 0; k < KC; k++) {
            float4 a0 = *(const float4*)&As[k][ty * 4];
            float4 a1 = *(const float4*)&As[k][64 + ty * 4];
            ulonglong2 bq0 = *(const ulonglong2*)&Bs[k][tx * 8];
            ulonglong2 bq1 = *(const ulonglong2*)&Bs[k][tx * 8 + 4];
            unsigned long long B[4] = {bq0.x, bq0.y, bq1.x, bq1.y};
            unsigned long long Ap[8];
            Ap[0] = pack2(a0.x, a0.x); Ap[1] = pack2(a0.y, a0.y);
            Ap[2] = pack2(a0.z, a0.z); Ap[3] = pack2(a0.w, a0.w);
            Ap[4] = pack2(a1.x, a1.x); Ap[5] = pack2(a1.y, a1.y);
            Ap[6] = pack2(a1.z, a1.z); Ap[7] = pack2(a1.w, a1.w);
#pragma unroll
            for (int i = 0; i < 8; i++)
#pragma unroll
                for (int j = 0; j < 4; j++)
                    acc[i][j] = fma2(Ap[i], B[j], acc[i][j]);
        }
        __syncthreads();
    }

    // --- epilogue ---
    float bv[8];
#pragma unroll
    for (int j = 0; j < 8; j++) bv[j] = BIAS ? bias[tx * 8 + j] : 0.f;

    float cs[8], cq[8];
#pragma unroll
    for (int j = 0; j < 8; j++) { cs[j] = 0.f; cq[j] = 0.f; }

#pragma unroll
    for (int i = 0; i < 8; i++) {
        int row = row0 + ((i < 4) ? (ty * 4 + i) : (64 + ty * 4 + i - 4));
        float v[8];
#pragma unroll
        for (int j = 0; j < 4; j++) unpack2(acc[i][j], v[2 * j], v[2 * j + 1]);
#pragma unroll
        for (int j = 0; j < 8; j++) {
            v[j] += bv[j];
            if (RELU) v[j] = fmaxf(v[j], 0.f);
        }
        if (row < N_NODES) {
            float4 o0 = make_float4(v[0], v[1], v[2], v[3]);
            float4 o1 = make_float4(v[4], v[5], v[6], v[7]);
            *(float4*)&C[row * DIM + tx * 8] = o0;
            *(float4*)&C[row * DIM + tx * 8 + 4] = o1;
            if (STATS >= 0) {
#pragma unroll
                for (int j = 0; j < 8; j++) { cs[j] += v[j]; cq[j] += v[j] * v[j]; }
            }
        }
    }

    if constexpr (STATS >= 0) {
#pragma unroll
        for (int j = 0; j < 8; j++) Sred[ty][tx * 8 + j] = cs[j];
        __syncthreads();
        if (tid < DIM) {
            float t = 0.f;
#pragma unroll
            for (int r = 0; r < 16; r++) t += Sred[r][tid];
            atomicAdd(&g_sum[STATS * DIM + tid], t);
        }
        __syncthreads();
#pragma unroll
        for (int j = 0; j < 8; j++) Sred[ty][tx * 8 + j] = cq[j];
        __syncthreads();
        if (tid < DIM) {
            float t = 0.f;
#pragma unroll
            for (int r = 0; r < 16; r++) t += Sred[r][tid];
            atomicAdd(&g_sumsq[STATS * DIM + tid], t);
        }
    }
}

// ---------------- BN finalize: fold into affine h = a*z + b ----------------
__global__ void k_bn_final(int layer, const float* __restrict__ gamma,
                           const float* __restrict__ beta) {
    int c = threadIdx.x;
    if (c < DIM) {
        float mu = g_sum[layer * DIM + c] * (1.f / N_NODES);
        float var = g_sumsq[layer * DIM + c] * (1.f / N_NODES) - mu * mu;
        float istd = rsqrtf(var + BN_EPS);
        float a = istd * gamma[c];
        g_a[layer * DIM + c] = a;
        g_b[layer * DIM + c] = beta[c] - mu * a;
    }
}

// ---------------- GCN aggregation ----------------
__global__ void k_gcn_agg(const float* __restrict__ h, const float* __restrict__ bias,
                          float* __restrict__ out) {
    int gt = blockIdx.x * blockDim.x + threadIdx.x;
    int node = gt >> 5;
    int lane = gt & 31;
    if (node >= N_NODES) return;
    float dn = g_dis[node];
    float4 acc = *(const float4*)&h[node * DIM + lane * 4];
    acc.x *= dn; acc.y *= dn; acc.z *= dn; acc.w *= dn;
    int e0 = g_rowptr[node], e1 = g_rowptr[node + 1];
    for (int e = e0; e < e1; e++) {
        int s = g_csrc[e];
        float ds = g_dis[s];
        float4 v = *(const float4*)&h[s * DIM + lane * 4];
        acc.x += v.x * ds; acc.y += v.y * ds;
        acc.z += v.z * ds; acc.w += v.w * ds;
    }
    float4 b = *(const float4*)&bias[lane * 4];
    float4 r;
    r.x = fmaxf(acc.x * dn + b.x, 0.f);
    r.y = fmaxf(acc.y * dn + b.y, 0.f);
    r.z = fmaxf(acc.z * dn + b.z, 0.f);
    r.w = fmaxf(acc.w * dn + b.w, 0.f);
    *(float4*)&out[node * DIM + lane * 4] = r;
}

// ---------------- GIN aggregation with folded BN affine ----------------
// out = a[c]*(z_i + sum z_s) + b[c]*(deg+1)
__global__ void k_gin_agg_affine(const float* __restrict__ z, int layer,
                                 float* __restrict__ out) {
    int gt = blockIdx.x * blockDim.x + threadIdx.x;
    int node = gt >> 5;
    int lane = gt & 31;
    if (node >= N_NODES) return;
    float4 acc = *(const float4*)&z[node * DIM + lane * 4];
    int e0 = g_rowptr[node], e1 = g_rowptr[node + 1];
    for (int e = e0; e < e1; e++) {
        int s = g_csrc[e];
        float4 v = *(const float4*)&z[s * DIM + lane * 4];
        acc.x += v.x; acc.y += v.y; acc.z += v.z; acc.w += v.w;
    }
    float4 a = *(const float4*)&g_a[layer * DIM + lane * 4];
    float4 b = *(const float4*)&g_b[layer * DIM + lane * 4];
    float m = (float)(e1 - e0 + 1);
    float4 r;
    r.x = a.x * acc.x + b.x * m;
    r.y = a.y * acc.y + b.y * m;
    r.z = a.z * acc.z + b.z * m;
    r.w = a.w * acc.w + b.w * m;
    *(float4*)&out[node * DIM + lane * 4] = r;
}

// ---------------- GIN layer-0 aggregation (F_IN=78) ----------------
__global__ void k_gin_agg78(const float* __restrict__ x, float* __restrict__ out) {
    int gt = blockIdx.x * blockDim.x + threadIdx.x;
    int node = gt >> 5;
    int lane = gt & 31;
    if (node >= N_NODES) return;
    bool has2 = (lane + 64) < F_IN;
    float a0 = x[node * F_IN + lane];
    float a1 = x[node * F_IN + lane + 32];
    float a2 = has2 ? x[node * F_IN + lane + 64] : 0.f;
    int e0 = g_rowptr[node], e1 = g_rowptr[node + 1];
    for (int e = e0; e < e1; e++) {
        int s = g_csrc[e];
        a0 += x[s * F_IN + lane];
        a1 += x[s * F_IN + lane + 32];
        if (has2) a2 += x[s * F_IN + lane + 64];
    }
    out[node * F_IN + lane] = a0;
    out[node * F_IN + lane + 32] = a1;
    if (has2) out[node * F_IN + lane + 64] = a2;
}

// ---------------- readout ----------------
__global__ void k_readout(float* __restrict__ out) {
    int g = blockIdx.x;
    int c = threadIdx.x;  // 128
    int r0 = g_gstart[g], r1 = g_gstart[g + 1];
    float a1c = g_a[0 * DIM + c], b1c = g_b[0 * DIM + c];
    float a2c = g_a[1 * DIM + c], b2c = g_b[1 * DIM + c];
    float a3c = g_a[2 * DIM + c], b3c = g_b[2 * DIM + c];
    float m1 = -INFINITY, m2 = -INFINITY, m3 = -INFINITY;
    float m4 = -INFINITY, m5 = -INFINITY, m6 = -INFINITY;
    float m7 = -INFINITY, m8 = -INFINITY, m9 = -INFINITY;
    for (int r = r0; r < r1; r++) {
        float a = fmaf(a1c, g_z1[r * DIM + c], b1c);
        float b = fmaf(a2c, g_z2[r * DIM + c], b2c);
        float d = fmaf(a3c, g_z3[r * DIM + c], b3c);
        float e1 = g_g1[r * DIM + c];
        float e2 = g_g2[r * DIM + c];
        m1 = fmaxf(m1, a); m2 = fmaxf(m2, b); m3 = fmaxf(m3, d);
        m4 = fmaxf(m4, a * b * d);
        m5 = fmaxf(m5, a + b + d);
        m6 = fmaxf(m6, e1); m7 = fmaxf(m7, e2);
        m8 = fmaxf(m8, e2 + e1); m9 = fmaxf(m9, e2 * e1);
    }
    float* o = out + (size_t)g * (9 * DIM);
    o[0 * DIM + c] = m1; o[1 * DIM + c] = m2; o[2 * DIM + c] = m3;
    o[3 * DIM + c] = m4; o[4 * DIM + c] = m5; o[5 * DIM + c] = m6;
    o[6 * DIM + c] = m7; o[7 * DIM + c] = m8; o[8 * DIM + c] = m9;
}

// ---------------- launch ----------------
extern "C" void kernel_launch(void* const* d_in, const int* in_sizes, int n_in,
                              void* d_out, int out_size) {
    const float* x = (const float*)d_in[0];
    const int* ei = (const int*)d_in[1];
    const int* src = ei;
    const int* dst = ei + N_EDGES;
    const int* batch = (const int*)d_in[2];
    int base = (n_in >= 18) ? 4 : 3;
    const float* gcn1_W = (const float*)d_in[base + 0];
    const float* gcn1_b = (const float*)d_in[base + 1];
    const float* gcn2_W = (const float*)d_in[base + 2];
    const float* gcn2_b = (const float*)d_in[base + 3];
    const float* gin0_w1 = (const float*)d_in[base + 4];
    const float* gin0_b1 = (const float*)d_in[base + 5];
    const float* gin0_w2 = (const float*)d_in[base + 6];
    const float* gin0_b2 = (const float*)d_in[base + 7];
    const float* gin_w1 = (const float*)d_in[base + 8];
    const float* gin_b1 = (const float*)d_in[base + 9];
    const float* gin_w2 = (const float*)d_in[base + 10];
    const float* gin_b2 = (const float*)d_in[base + 11];
    const float* bn_gamma = (const float*)d_in[base + 12];
    const float* bn_beta = (const float*)d_in[base + 13];
    float* out = (float*)d_out;

    float *t0 = nullptr, *t1 = nullptr, *g1 = nullptr, *g2 = nullptr;
    float *z1 = nullptr, *z2 = nullptr, *z3 = nullptr;
    cudaGetSymbolAddress((void**)&t0, g_t0);
    cudaGetSymbolAddress((void**)&t1, g_t1);
    cudaGetSymbolAddress((void**)&g1, g_g1);
    cudaGetSymbolAddress((void**)&g2, g_g2);
    cudaGetSymbolAddress((void**)&z1, g_z1);
    cudaGetSymbolAddress((void**)&z2, g_z2);
    cudaGetSymbolAddress((void**)&z3, g_z3);

    const int NB_N = (N_NODES + 255) / 256;
    const int NB_E = (N_EDGES + 255) / 256;
    const int NB_GEMM = (N_NODES + TM - 1) / TM;
    const int NB_AGG = (N_NODES * 32 + 255) / 256;
    const int SCAN_BLOCKS = (N_NODES + 1023) / 1024;

    // --- CSR build + degrees + stat zeroing ---
    k_init<<<NB_N, 256>>>();
    k_hist<<<NB_E, 256>>>(dst);
    k_dis<<<NB_N, 256>>>();
    k_scan1<<<SCAN_BLOCKS, 1024>>>();
    k_scan2<<<1, 1>>>(SCAN_BLOCKS);
    k_scan3<<<NB_N, 256>>>();
    k_scatter<<<NB_E, 256>>>(src, dst);
    k_gstart<<<(N_GRAPHS + 1 + 255) / 256, 256>>>(batch);

    // --- GCN1 / GCN2 ---
    k_gemm<F_IN, false, false, -1><<<NB_GEMM, 256>>>(x, gcn1_W, nullptr, t0);
    k_gcn_agg<<<NB_AGG, 256>>>(t0, gcn1_b, g1);
    k_gemm<DIM, false, false, -1><<<NB_GEMM, 256>>>(g1, gcn2_W, nullptr, t0);
    k_gcn_agg<<<NB_AGG, 256>>>(t0, gcn2_b, g2);

    // --- GIN layer 0 ---
    k_gin_agg78<<<NB_AGG, 256>>>(x, t1);
    k_gemm<F_IN, true, true, -1><<<NB_GEMM, 256>>>(t1, gin0_w1, gin0_b1, t0);
    k_gemm<DIM, true, true, 0><<<NB_GEMM, 256>>>(t0, gin0_w2, gin0_b2, z1);
    k_bn_final<<<1, 128>>>(0, bn_gamma + 0 * DIM, bn_beta + 0 * DIM);

    // --- GIN layer 1 ---
    k_gin_agg_affine<<<NB_AGG, 256>>>(z1, 0, t0);
    k_gemm<DIM, true, true, -1><<<NB_GEMM, 256>>>(t0, gin_w1 + 0 * DIM * DIM, gin_b1 + 0 * DIM, t1);
    k_gemm<DIM, true, true, 1><<<NB_GEMM, 256>>>(t1, gin_w2 + 0 * DIM * DIM, gin_b2 + 0 * DIM, z2);
    k_bn_final<<<1, 128>>>(1, bn_gamma + 1 * DIM, bn_beta + 1 * DIM);

    // --- GIN layer 2 ---
    k_gin_agg_affine<<<NB_AGG, 256>>>(z2, 1, t0);
    k_gemm<DIM, true, true, -1><<<NB_GEMM, 256>>>(t0, gin_w1 + 1 * DIM * DIM, gin_b1 + 1 * DIM, t1);
    k_gemm<DIM, true, true, 2><<<NB_GEMM, 256>>>(t1, gin_w2 + 1 * DIM * DIM, gin_b2 + 1 * DIM, z3);
    k_bn_final<<<1, 128>>>(2, bn_gamma + 2 * DIM, bn_beta + 2 * DIM);

    // --- readout ---
    k_readout<<<N_GRAPHS, 128>>>(out);
}